// round 2
// baseline (speedup 1.0000x reference)
#include <cuda_runtime.h>
#include <math_constants.h>

// Sparsemax (faithful to the reference's unsorted math) over the last axis.
// x: (R, 2048) fp32 rows, R = 8*1024. One CTA per row, 256 threads, 8 elts/thread.
// Single read + single write of the 64MB tensor => HBM-roofline bound.

#define ROW_K   2048
#define TPB     256
#define EPT     8          // ROW_K / TPB
#define NWARP   (TPB / 32)

__global__ void __launch_bounds__(TPB, 8)
sparsemax_row_kernel(const float* __restrict__ x, float* __restrict__ out)
{
    __shared__ float s_wsum[NWARP];   // warp partial sums for the scan
    __shared__ float s_rk[NWARP];     // per-warp kmax
    __shared__ float s_rt[NWARP];     // per-warp tmax
    __shared__ float s_tau;

    const int tid  = threadIdx.x;
    const int lane = tid & 31;
    const int warp = tid >> 5;

    const size_t row_off = (size_t)blockIdx.x * ROW_K;
    const float4* __restrict__ xin  = (const float4*)(x   + row_off);
    float4*       __restrict__ xout = (float4*)      (out + row_off);

    // ---- load 8 contiguous floats (two float4s) into registers ----
    float4 a = xin[tid * 2 + 0];
    float4 b = xin[tid * 2 + 1];
    float z[EPT] = { a.x, a.y, a.z, a.w, b.x, b.y, b.z, b.w };

    // ---- thread-local sequential sum ----
    float tot = 0.0f;
    #pragma unroll
    for (int e = 0; e < EPT; ++e) tot = __fadd_rn(tot, z[e]);

    // ---- warp inclusive scan of thread totals ----
    float inc = tot;
    #pragma unroll
    for (int d = 1; d < 32; d <<= 1) {
        float v = __shfl_up_sync(0xffffffffu, inc, d);
        if (lane >= d) inc += v;
    }
    if (lane == 31) s_wsum[warp] = inc;
    __syncthreads();

    // ---- scan the NWARP warp sums (warp 0, lanes 0..NWARP-1 hold data;
    //      full-mask shuffles, inactive lanes carry garbage harmlessly) ----
    if (warp == 0) {
        float v = (lane < NWARP) ? s_wsum[lane] : 0.0f;
        #pragma unroll
        for (int d = 1; d < NWARP; d <<= 1) {
            float u = __shfl_up_sync(0xffffffffu, v, d);
            if (lane >= d) v += u;
        }
        if (lane < NWARP) s_wsum[lane] = v;   // inclusive warp-sum scan
    }
    __syncthreads();

    // exclusive carry into this thread's first element
    float carry = inc - tot;
    if (warp > 0) carry += s_wsum[warp - 1];

    // ---- mask + reductions, sequential running sum from the carry ----
    // left  = 1 + (k+1)*z[k]   (separate mul+add roundings, matching the ref)
    // right = cumsum(z)[k]
    // mask  = left <= right ; kmax/tmax over !mask
    float kmax = 0.0f;
    float tmax = -CUDART_INF_F;
    float run  = carry;
    const int base = tid * EPT;
    #pragma unroll
    for (int e = 0; e < EPT; ++e) {
        run = __fadd_rn(run, z[e]);
        float kk   = (float)(base + e + 1);
        float left = __fadd_rn(1.0f, __fmul_rn(kk, z[e]));
        if (!(left <= run)) {
            kmax = fmaxf(kmax, kk);
            tmax = fmaxf(tmax, run);
        }
    }

    // ---- block max-reduce (kmax, tmax) ----
    #pragma unroll
    for (int d = 16; d > 0; d >>= 1) {
        kmax = fmaxf(kmax, __shfl_xor_sync(0xffffffffu, kmax, d));
        tmax = fmaxf(tmax, __shfl_xor_sync(0xffffffffu, tmax, d));
    }
    if (lane == 0) { s_rk[warp] = kmax; s_rt[warp] = tmax; }
    __syncthreads();
    if (tid == 0) {
        float km = s_rk[0], tm = s_rt[0];
        #pragma unroll
        for (int w = 1; w < NWARP; ++w) {
            km = fmaxf(km, s_rk[w]);
            tm = fmaxf(tm, s_rt[w]);
        }
        s_tau = __fdiv_rn(__fadd_rn(tm, -1.0f), km);
    }
    __syncthreads();
    const float tau = s_tau;

    // ---- out = relu(x - tau), two float4 stores ----
    #pragma unroll
    for (int e = 0; e < EPT; ++e) z[e] = fmaxf(z[e] - tau, 0.0f);
    float4 oa = { z[0], z[1], z[2], z[3] };
    float4 ob = { z[4], z[5], z[6], z[7] };
    xout[tid * 2 + 0] = oa;
    xout[tid * 2 + 1] = ob;
}

extern "C" void kernel_launch(void* const* d_in, const int* in_sizes, int n_in,
                              void* d_out, int out_size)
{
    const float* x = (const float*)d_in[0];
    float* out = (float*)d_out;
    int rows = (in_sizes && in_sizes[0] > 0) ? (in_sizes[0] / ROW_K) : (out_size / ROW_K);
    sparsemax_row_kernel<<<rows, TPB>>>(x, out);
}

// round 5
// speedup vs baseline: 1.0654x; 1.0654x over previous
#include <cuda_runtime.h>
#include <math_constants.h>

// Sparsemax (faithful unsorted math) over the last axis.
// x: (8192, 2048) fp32 rows. One CTA/row, 256 threads, 8 elts/thread,
// row register-resident: single read + single write of the 64MB tensor.
// R5 = resubmission of R4 (untested due to infra failure):
// redux.sync reductions via intrinsics only, 2 barriers, no tau broadcast.

#define ROW_K   2048
#define TPB     256
#define EPT     8          // ROW_K / TPB
#define NWARP   (TPB / 32)

// Order-preserving float -> uint key (exact, handles -inf/negatives):
// for v >= 0: bits | 0x80000000 ; for v < 0: ~bits. Monotone in float order.
__device__ __forceinline__ unsigned f32_order_key(float v) {
    unsigned b = __float_as_uint(v);
    return b ^ (((int)b >> 31) | 0x80000000u);
}
__device__ __forceinline__ float f32_from_key(unsigned k) {
    unsigned b = k ^ ((~(int)k >> 31) | 0x80000000u);
    return __uint_as_float(b);
}

__global__ void __launch_bounds__(TPB, 8)
sparsemax_row_kernel(const float* __restrict__ x, float* __restrict__ out)
{
    __shared__ float s_wsum[NWARP];   // per-warp data totals
    __shared__ float s_rk[NWARP];     // per-warp kmax
    __shared__ float s_rt[NWARP];     // per-warp tmax

    const int tid  = threadIdx.x;
    const int lane = tid & 31;
    const int warp = tid >> 5;

    const size_t row_off = (size_t)blockIdx.x * ROW_K;
    const float4* __restrict__ xin  = (const float4*)(x   + row_off);
    float4*       __restrict__ xout = (float4*)      (out + row_off);

    // ---- load 8 contiguous floats (two float4s) into registers ----
    float4 a = xin[tid * 2 + 0];
    float4 b = xin[tid * 2 + 1];
    float z[EPT] = { a.x, a.y, a.z, a.w, b.x, b.y, b.z, b.w };

    // ---- thread-local sequential sum (matches reference eval order) ----
    float tot = 0.0f;
    #pragma unroll
    for (int e = 0; e < EPT; ++e) tot = __fadd_rn(tot, z[e]);

    // ---- warp inclusive scan of thread totals (5 shfl) ----
    float inc = tot;
    #pragma unroll
    for (int d = 1; d < 32; d <<= 1) {
        float v = __shfl_up_sync(0xffffffffu, inc, d);
        if (lane >= d) inc += v;
    }
    if (lane == 31) s_wsum[warp] = inc;   // warp total
    __syncthreads();                      // barrier #1

    // exclusive carry: prior threads in warp + totals of prior warps
    float carry = inc - tot;
    #pragma unroll
    for (int w = 0; w < NWARP; ++w)
        if (w < warp) carry += s_wsum[w];  // broadcast LDS, no extra scan/barrier

    // ---- mask + partial reductions, sequential running sum from carry ----
    // left  = 1 + (k+1)*z[k]  (separate mul+add roundings, matching the ref)
    // right = cumsum(z)[k] ; mask = left <= right ; kmax/tmax over !mask
    unsigned kmaxi = 0u;
    float tmax = -CUDART_INF_F;
    float run  = carry;
    const int base = tid * EPT;
    #pragma unroll
    for (int e = 0; e < EPT; ++e) {
        run = __fadd_rn(run, z[e]);
        const unsigned kk = (unsigned)(base + e + 1);
        float left = __fadd_rn(1.0f, __fmul_rn((float)kk, z[e]));
        if (!(left <= run)) {
            kmaxi = max(kmaxi, kk);
            tmax  = fmaxf(tmax, run);
        }
    }

    // ---- warp reduce via single-instruction REDUX (integer, order-keyed) ----
    kmaxi = __reduce_max_sync(0xffffffffu, kmaxi);
    unsigned tkey = __reduce_max_sync(0xffffffffu, f32_order_key(tmax));
    if (lane == 0) { s_rk[warp] = (float)kmaxi; s_rt[warp] = f32_from_key(tkey); }
    __syncthreads();                      // barrier #2

    // ---- every thread folds the 8 warp results and computes tau ----
    float km = s_rk[0], tm = s_rt[0];
    #pragma unroll
    for (int w = 1; w < NWARP; ++w) {
        km = fmaxf(km, s_rk[w]);
        tm = fmaxf(tm, s_rt[w]);
    }
    const float tau = __fdiv_rn(__fadd_rn(tm, -1.0f), km);

    // ---- out = relu(x - tau), two float4 stores ----
    #pragma unroll
    for (int e = 0; e < EPT; ++e) z[e] = fmaxf(z[e] - tau, 0.0f);
    float4 oa = { z[0], z[1], z[2], z[3] };
    float4 ob = { z[4], z[5], z[6], z[7] };
    xout[tid * 2 + 0] = oa;
    xout[tid * 2 + 1] = ob;
}

extern "C" void kernel_launch(void* const* d_in, const int* in_sizes, int n_in,
                              void* d_out, int out_size)
{
    const float* x = (const float*)d_in[0];
    float* out = (float*)d_out;
    int rows = (in_sizes && in_sizes[0] > 0) ? (in_sizes[0] / ROW_K) : (out_size / ROW_K);
    sparsemax_row_kernel<<<rows, TPB>>>(x, out);
}